// round 3
// baseline (speedup 1.0000x reference)
#include <cuda_runtime.h>
#include <math.h>

// Problem constants
#define B 32
#define S 2048
#define H 1024
#define R 64
#define HV4 (H / 4)          // 256 float4 per row
#define ROWS_PER_BLK 8       // rows of d computed per block in k_d_scores

// Scratch (no allocations allowed -> __device__ globals)
__device__ float g_ae[B * H];            // answer_emb [B,H]
__device__ float g_u[B * H];             // u = W @ answer_emb, [B,H]
__device__ float g_d[B * S];             // per-row dot d[b,s] (touched rows only)
__device__ int   g_list[B * S];          // per-batch compacted touched-row list
__device__ int   g_cnt[B];               // touched-row count per batch
__device__ int   g_nblk[B];              // active d-blocks per batch
__device__ int   g_arrive[B];            // arrival counters (zeroed in K1 each call)
__device__ unsigned char g_mask[B * R];  // canonicalized rubric_mask

__device__ __forceinline__ float dot4(float4 a, float4 b) {
    return a.x * b.x + a.y * b.y + a.z * b.z + a.w * b.w;
}

// ---------------------------------------------------------------------------
// K1 (fused prep). 64 blocks x 256 threads.
//   blocks [0,32): answer-span mean pooling for batch b = blockIdx.x
//   blocks [32,64): for batch b = blockIdx.x-32:
//       - canonicalize rubric_mask (detect 1-byte bool vs int32 encoding)
//       - mark the union of valid rubric-span rows (smem flags)
//       - compact into g_list[b], set g_cnt/g_nblk, zero g_arrive
// ---------------------------------------------------------------------------
__global__ void k_prep(const float* __restrict__ seq,
                       const int* __restrict__ aspan,
                       const int* __restrict__ rspan,
                       const unsigned char* __restrict__ rawmask) {
    int tid = threadIdx.x;

    if (blockIdx.x < 32) {
        // ---- answer pooling: thread t owns float4 column t ----
        int b = blockIdx.x;
        int s0 = __ldg(aspan + b * 2), s1 = __ldg(aspan + b * 2 + 1);
        float inv = 1.0f / (float)(s1 - s0);
        const float4* base = (const float4*)(seq + (size_t)b * S * H) + tid;
        float4 a0 = make_float4(0, 0, 0, 0), a1 = a0, a2 = a0, a3 = a0;
        int s = s0;
        for (; s + 4 <= s1; s += 4) {
            float4 e0 = __ldg(base + (s + 0) * HV4);
            float4 e1 = __ldg(base + (s + 1) * HV4);
            float4 e2 = __ldg(base + (s + 2) * HV4);
            float4 e3 = __ldg(base + (s + 3) * HV4);
            a0.x += e0.x; a0.y += e0.y; a0.z += e0.z; a0.w += e0.w;
            a1.x += e1.x; a1.y += e1.y; a1.z += e1.z; a1.w += e1.w;
            a2.x += e2.x; a2.y += e2.y; a2.z += e2.z; a2.w += e2.w;
            a3.x += e3.x; a3.y += e3.y; a3.z += e3.z; a3.w += e3.w;
        }
        for (; s < s1; s++) {
            float4 e = __ldg(base + s * HV4);
            a0.x += e.x; a0.y += e.y; a0.z += e.z; a0.w += e.w;
        }
        float4 rv;
        rv.x = (a0.x + a1.x + a2.x + a3.x) * inv;
        rv.y = (a0.y + a1.y + a2.y + a3.y) * inv;
        rv.z = (a0.z + a1.z + a2.z + a3.z) * inv;
        rv.w = (a0.w + a1.w + a2.w + a3.w) * inv;
        ((float4*)g_ae)[b * HV4 + tid] = rv;
        return;
    }

    // ---- mark + compact for batch b ----
    int b = blockIdx.x - 32;

    // Encoding detection over the first 2048 bytes (safe under both encodings):
    // int32-coded {0,1} has all bytes at i%4!=0 equal to zero; a 1-byte bool
    // mask (~80% true) has nonzero bytes there with overwhelming probability.
    __shared__ int s_any;
    if (tid == 0) s_any = 0;
    __syncthreads();
    int any = 0;
    for (int i = tid; i < B * R; i += 256)
        if (i & 3) any |= rawmask[i];
    if (any) atomicOr(&s_any, 1);
    __syncthreads();
    const int is_bool = s_any;
    const int* raw32 = (const int*)rawmask;

    __shared__ unsigned char fl[S];
    for (int i = tid; i < S / 4; i += 256) ((int*)fl)[i] = 0;
    __syncthreads();

    if (tid < R) {
        int gi = b * R + tid;
        unsigned char m = is_bool ? (rawmask[gi] != 0) : (raw32[gi] != 0);
        g_mask[gi] = m;
        if (m) {
            int s0 = __ldg(rspan + gi * 2), s1 = __ldg(rspan + gi * 2 + 1);
            for (int s = s0; s < s1; s++) fl[s] = 1;
        }
    }
    __syncthreads();

    // compact: thread t owns positions [t*8, t*8+8)
    int basep = tid * 8;
    int c = 0;
    #pragma unroll
    for (int k = 0; k < 8; k++) c += fl[basep + k];

    int lane = tid & 31, wid = tid >> 5;
    int v = c;
    #pragma unroll
    for (int o = 1; o < 32; o <<= 1) {
        int n = __shfl_up_sync(0xffffffffu, v, o);
        if (lane >= o) v += n;
    }
    __shared__ int wsum[8], wpref[9];
    if (lane == 31) wsum[wid] = v;
    __syncthreads();
    if (tid == 0) {
        int acc = 0;
        for (int w = 0; w < 8; w++) { wpref[w] = acc; acc += wsum[w]; }
        wpref[8] = acc;
    }
    __syncthreads();

    int rank = wpref[wid] + v - c;  // exclusive prefix
    int* list = g_list + b * S;
    #pragma unroll
    for (int k = 0; k < 8; k++)
        if (fl[basep + k]) list[rank++] = basep + k;

    if (tid == 0) {
        int cnt = wpref[8];
        g_cnt[b] = cnt;
        g_nblk[b] = (cnt + ROWS_PER_BLK - 1) / ROWS_PER_BLK;
        g_arrive[b] = 0;
    }
}

// ---------------------------------------------------------------------------
// K2: u[b,h] = sum_k W[h,k] * ae[b,k]. W read exactly once from HBM.
// 256 blocks x 256 threads; warp w owns 4 batches.
// ---------------------------------------------------------------------------
__global__ void k_u(const float* __restrict__ W) {
    int h0 = blockIdx.x * 4;
    int wrp = threadIdx.x >> 5;
    int lane = threadIdx.x & 31;
    int bbase = wrp * 4;

    const float4* a0 = (const float4*)(g_ae + (size_t)(bbase + 0) * H);
    const float4* a1 = (const float4*)(g_ae + (size_t)(bbase + 1) * H);
    const float4* a2 = (const float4*)(g_ae + (size_t)(bbase + 2) * H);
    const float4* a3 = (const float4*)(g_ae + (size_t)(bbase + 3) * H);

    for (int hh = 0; hh < 4; hh++) {
        int h = h0 + hh;
        const float4* wrow = (const float4*)(W + (size_t)h * H);
        float acc0 = 0.f, acc1 = 0.f, acc2 = 0.f, acc3 = 0.f;
        #pragma unroll
        for (int kc = 0; kc < 8; kc++) {
            int ki = kc * 32 + lane;
            float4 w4 = __ldg(wrow + ki);
            acc0 += dot4(w4, __ldg(a0 + ki));
            acc1 += dot4(w4, __ldg(a1 + ki));
            acc2 += dot4(w4, __ldg(a2 + ki));
            acc3 += dot4(w4, __ldg(a3 + ki));
        }
        #pragma unroll
        for (int off = 16; off; off >>= 1) {
            acc0 += __shfl_xor_sync(0xffffffffu, acc0, off);
            acc1 += __shfl_xor_sync(0xffffffffu, acc1, off);
            acc2 += __shfl_xor_sync(0xffffffffu, acc2, off);
            acc3 += __shfl_xor_sync(0xffffffffu, acc3, off);
        }
        if (lane == 0) {
            g_u[(size_t)(bbase + 0) * H + h] = acc0;
            g_u[(size_t)(bbase + 1) * H + h] = acc1;
            g_u[(size_t)(bbase + 2) * H + h] = acc2;
            g_u[(size_t)(bbase + 3) * H + h] = acc3;
        }
    }
}

// ---------------------------------------------------------------------------
// K3 (fused): per-unique-row dots d[b,s], then the LAST-arriving block of each
// batch computes the 64 rubric scores + softmax for that batch.
// Grid (ceil(S/8), B) x 256 threads; warp j handles touched row base+j.
// Release: __threadfence + atomicAdd. Acquire: atomic + __threadfence + __ldcg.
// Deterministic: scores/softmax computed by exactly one block in fixed order.
// ---------------------------------------------------------------------------
__global__ void k_d_scores(const float* __restrict__ seq,
                           const int* __restrict__ rspan,
                           float* __restrict__ out) {
    int b = blockIdx.y;
    int cnt = g_cnt[b];
    int base = blockIdx.x * ROWS_PER_BLK;
    if (base >= cnt) return;

    int tid = threadIdx.x, wid = tid >> 5, lane = tid & 31;
    int k = base + wid;
    if (k < cnt) {
        int s = g_list[b * S + k];
        const float4* row = (const float4*)(seq + ((size_t)b * S + s) * H);
        const float4* u = (const float4*)(g_u + (size_t)b * H);
        float acc = 0.f;
        #pragma unroll
        for (int i = 0; i < 8; i++) {
            int idx4 = i * 32 + lane;
            acc += dot4(__ldg(row + idx4), __ldg(u + idx4));
        }
        #pragma unroll
        for (int off = 16; off; off >>= 1)
            acc += __shfl_xor_sync(0xffffffffu, acc, off);
        if (lane == 0) g_d[b * S + s] = acc;
    }
    __syncthreads();

    __shared__ int s_last;
    if (tid == 0) {
        __threadfence();
        int old = atomicAdd(&g_arrive[b], 1);
        s_last = (old == g_nblk[b] - 1);
    }
    __syncthreads();
    if (!s_last) return;
    __threadfence();  // acquire side

    // ---- scores: 4 threads per rubric (r = tid>>2, j = tid&3) ----
    __shared__ float sc[R];
    int r = tid >> 2, j = tid & 3;
    {
        int gi = b * R + r;
        bool m = g_mask[gi] != 0;
        float val = -INFINITY;
        float part = 0.f;
        int s0 = __ldg(rspan + gi * 2), s1 = __ldg(rspan + gi * 2 + 1);
        if (m)
            for (int s = s0 + j; s < s1; s += 4)
                part += __ldcg(g_d + b * S + s);
        part += __shfl_xor_sync(0xffffffffu, part, 1);
        part += __shfl_xor_sync(0xffffffffu, part, 2);
        if (m) val = part / (float)(s1 - s0);
        if (j == 0) sc[r] = val;
    }
    __syncthreads();

    // ---- softmax over 64 by warp 0 (2 values per lane) ----
    if (wid == 0) {
        float v0 = sc[lane], v1 = sc[lane + 32];
        float m = fmaxf(v0, v1);
        #pragma unroll
        for (int off = 16; off; off >>= 1)
            m = fmaxf(m, __shfl_xor_sync(0xffffffffu, m, off));
        float e0 = expf(v0 - m), e1 = expf(v1 - m);  // expf(-inf)=0
        float sum = e0 + e1;
        #pragma unroll
        for (int off = 16; off; off >>= 1)
            sum += __shfl_xor_sync(0xffffffffu, sum, off);
        float invs = 1.0f / sum;
        out[b * R + lane] = e0 * invs;
        out[b * R + lane + 32] = e1 * invs;
    }
}

// ---------------------------------------------------------------------------
// Launch. Inputs identified by unique element counts (robust to ordering):
//   seq: 67108864, W: 1048576, b: 1, rubric_span: 4096, answer_span: 64,
//   rubric_mask: 2048
// ---------------------------------------------------------------------------
extern "C" void kernel_launch(void* const* d_in, const int* in_sizes, int n_in,
                              void* d_out, int out_size) {
    const float* seq = nullptr;
    const float* W = nullptr;
    const int* rspan = nullptr;
    const int* aspan = nullptr;
    const unsigned char* mask = nullptr;

    for (int i = 0; i < n_in; i++) {
        switch (in_sizes[i]) {
            case B * S * H: seq   = (const float*)d_in[i]; break;
            case H * H:     W     = (const float*)d_in[i]; break;
            case B * R * 2: rspan = (const int*)d_in[i]; break;
            case B * 2:     aspan = (const int*)d_in[i]; break;
            case B * R:     mask  = (const unsigned char*)d_in[i]; break;
            default: break;  // bias (size 1): cancels in softmax
        }
    }

    float* out = (float*)d_out;

    k_prep<<<64, 256>>>(seq, aspan, rspan, mask);
    k_u<<<H / 4, 256>>>(W);
    dim3 gd(S / ROWS_PER_BLK, B);
    k_d_scores<<<gd, 256>>>(seq, rspan, out);
}